// round 16
// baseline (speedup 1.0000x reference)
#include <cuda_runtime.h>
#include <cuda_bf16.h>
#include <math.h>
#include <stdint.h>

// Problem constants
#define B   256
#define S   512
#define D   768
#define D4  192          // float4 per row
#define K4D 3072         // 4*D
#define H1  256
#define H2  64
#define L   4

// GEMM1 tiling
#define BM  32
#define BN  64
#define BK  32
#define KS  16
#define KC  192          // k per split
#define NT  6            // k-tiles per job
#define FS  68           // padded fsh2 row stride (floats)

#define GRID 128         // <= 148 SMs -> co-residency guaranteed at 1 block/SM
#define GEMM_GRP_FLOATS (2*BK*FS + 2*BK*BN)   // 8448 floats = 33792 B per group
#define DSM_BYTES (4 * GEMM_GRP_FLOATS * 4)   // 135168 B (max phase: gemm, 4 groups)

// Scratch (device globals — no allocation allowed)
__device__ float g_f[B * K4D];            // features [256, 3072]
__device__ float g_h1p[KS * B * H1];      // GEMM1 partials [16, 256, 256]
__device__ unsigned g_cnt = 0;            // grid barrier arrival counter
__device__ unsigned g_gen = 0;            // grid barrier generation (monotonic)

#define FFMA2(d, a, b) \
    asm("fma.rn.f32x2 %0, %1, %2, %0;" : "+l"(d) : "l"(a), "l"(b))

// Sense-reversing grid barrier. GRID=128 <= #SMs, so all blocks are resident
// even at 1 block/SM — no deadlock possible from occupancy rounding.
// g_cnt resets every barrier; g_gen grows monotonically across graph replays.
__device__ __forceinline__ void grid_barrier() {
    __syncthreads();
    if (threadIdx.x == 0) {
        __threadfence();
        unsigned gen = *(volatile unsigned*)&g_gen;
        unsigned old = atomicAdd(&g_cnt, 1u);
        if (old == GRID - 1) {
            atomicExch(&g_cnt, 0u);
            __threadfence();
            atomicAdd(&g_gen, 1u);
        } else {
            while (*(volatile unsigned*)&g_gen == gen) { __nanosleep(20); }
        }
        __threadfence();
    }
    __syncthreads();
}

#define GRP_BAR() asm volatile("bar.sync %0, 128;" :: "r"(grp + 1) : "memory")

// ---------------------------------------------------------------------------
// ONE persistent kernel: feat -> barrier -> gemm1 -> barrier -> tail
// grid = 128 blocks x 512 threads.
// ---------------------------------------------------------------------------
__global__ void __launch_bounds__(512, 1) fused_kernel(
    const float* __restrict__ x1, const float* __restrict__ x2,
    const int* __restrict__ s1a, const int* __restrict__ e1a,
    const int* __restrict__ s2a, const int* __restrict__ e2a,
    const float* __restrict__ W1, const float* __restrict__ b1,
    const float* __restrict__ W2, const float* __restrict__ b2,
    const float* __restrict__ W3, const float* __restrict__ b3,
    float* __restrict__ out)
{
    extern __shared__ char dsm[];
    const int bx = blockIdx.x;
    const int t  = threadIdx.x;

    // =====================================================================
    // Phase 1: features. Half-block (256 thr) per sample, 2 samples/block.
    // thread map inside half: cg = tt%64 (3 float4 cols), rg = tt/64 (rows)
    // 6 independent loads in flight per iteration (3 cols x 2 sels).
    // Both halves execute identical barrier sequences -> __syncthreads ok.
    // =====================================================================
    {
        const int samp = t >> 8;          // 0/1
        const int tt   = t & 255;
        const int b    = bx * 2 + samp;

        // per-sample smem: float4 part[2][4][192] = 24576 B
        float4* part = reinterpret_cast<float4*>(dsm + samp * 24576);

        const float4* x4a = reinterpret_cast<const float4*>(x1);
        const float4* x4b = reinterpret_cast<const float4*>(x2);
        float4* f4 = reinterpret_cast<float4*>(g_f);
        const long base = (long)b * S * D4;
        const long frow = (long)b * (K4D / 4);

        int sA = s1a[b], eA = e1a[b];
        int sB = s2a[b], eB = e2a[b];
        eA = max(eA, sA + 1); int loA = max(sA, 0), hiA = min(eA, S);
        eB = max(eB, sB + 1); int loB = max(sB, 0), hiB = min(eB, S);
        float invA = 1.0f / (float)max(hiA - loA, 1);
        float invB = 1.0f / (float)max(hiB - loB, 1);

        // CLS rows: 384 items (2 sels x 192 cols) over 256 threads
        #pragma unroll
        for (int i = tt; i < 2 * D4; i += 256) {
            int sel = (i >= D4);
            int c = i - sel * D4;
            f4[frow + sel * (2 * D4) + c] = sel ? x4b[base + c] : x4a[base + c];
        }

        // span partial sums
        const int cg = tt & 63;
        const int rg = tt >> 6;
        const int c0 = cg * 3;

        float4 aA0 = {0,0,0,0}, aA1 = {0,0,0,0}, aA2 = {0,0,0,0};
        float4 aB0 = {0,0,0,0}, aB1 = {0,0,0,0}, aB2 = {0,0,0,0};
        int rA = loA + rg, rB = loB + rg;
        for (;;) {
            bool pa = rA < hiA, pb = rB < hiB;
            if (!pa && !pb) break;
            if (pa) {
                const float4* p = &x4a[base + (long)rA * D4 + c0];
                float4 v0 = p[0], v1 = p[1], v2 = p[2];
                aA0.x += v0.x; aA0.y += v0.y; aA0.z += v0.z; aA0.w += v0.w;
                aA1.x += v1.x; aA1.y += v1.y; aA1.z += v1.z; aA1.w += v1.w;
                aA2.x += v2.x; aA2.y += v2.y; aA2.z += v2.z; aA2.w += v2.w;
            }
            if (pb) {
                const float4* p = &x4b[base + (long)rB * D4 + c0];
                float4 v0 = p[0], v1 = p[1], v2 = p[2];
                aB0.x += v0.x; aB0.y += v0.y; aB0.z += v0.z; aB0.w += v0.w;
                aB1.x += v1.x; aB1.y += v1.y; aB1.z += v1.z; aB1.w += v1.w;
                aB2.x += v2.x; aB2.y += v2.y; aB2.z += v2.z; aB2.w += v2.w;
            }
            rA += 4; rB += 4;
        }
        part[(0 * 4 + rg) * D4 + c0 + 0] = aA0;
        part[(0 * 4 + rg) * D4 + c0 + 1] = aA1;
        part[(0 * 4 + rg) * D4 + c0 + 2] = aA2;
        part[(1 * 4 + rg) * D4 + c0 + 0] = aB0;
        part[(1 * 4 + rg) * D4 + c0 + 1] = aB1;
        part[(1 * 4 + rg) * D4 + c0 + 2] = aB2;
        __syncthreads();

        // reduce rowgroups + scale + store mean: 384 items per half
        #pragma unroll
        for (int i = tt; i < 2 * D4; i += 256) {
            int sel = (i >= D4);
            int c = i - sel * D4;
            float inv = sel ? invB : invA;
            float4 p0 = part[(sel * 4 + 0) * D4 + c];
            float4 p1 = part[(sel * 4 + 1) * D4 + c];
            float4 p2 = part[(sel * 4 + 2) * D4 + c];
            float4 p3 = part[(sel * 4 + 3) * D4 + c];
            float4 o;
            o.x = ((p0.x + p1.x) + (p2.x + p3.x)) * inv;
            o.y = ((p0.y + p1.y) + (p2.y + p3.y)) * inv;
            o.z = ((p0.z + p1.z) + (p2.z + p3.z)) * inv;
            o.w = ((p0.w + p1.w) + (p2.w + p3.w)) * inv;
            f4[frow + sel * (2 * D4) + D4 + c] = o;
        }
    }

    grid_barrier();

    // =====================================================================
    // Phase 2: GEMM1 split-K16. 512 jobs; 4 independent 128-thread groups
    // per block, one job each. Double-buffered smem, FFMA2 micro-kernel.
    // =====================================================================
    {
        const int grp = t >> 7;           // 0..3
        const int tid = t & 127;
        float* gbase = reinterpret_cast<float*>(dsm) + grp * GEMM_GRP_FLOATS;
        float (*fsh2)[FS] = reinterpret_cast<float(*)[FS]>(gbase);               // [2*BK][FS]
        float (*wsh)[BN]  = reinterpret_cast<float(*)[BN]>(gbase + 2 * BK * FS); // [2*BK][BN]

        const int job = bx * 4 + grp;         // 0..511
        const int kz  = job >> 5;             // 0..15
        const int rem = job & 31;
        const int m0  = (rem >> 2) * BM;
        const int n0  = (rem & 3) * BN;
        const int k0  = kz * KC;

        const int tx = tid % 16;
        const int ty = tid / 16;
        const int kq   = tid % 8;
        const int mrow = tid / 8;
        const int nq  = tid % 16;
        const int kr0 = tid / 16;

        const float4* gf4 = reinterpret_cast<const float4*>(g_f);
        const float4* w4  = reinterpret_cast<const float4*>(W1);

        unsigned long long acc2[4][2];
        #pragma unroll
        for (int r = 0; r < 4; ++r) { acc2[r][0] = 0ull; acc2[r][1] = 0ull; }

        float4 fv[2];
        float4 wv[4];

        // prologue: load + stage tile 0 into buffer 0
        #pragma unroll
        for (int i = 0; i < 2; ++i) {
            int m = mrow + i * 16;
            fv[i] = gf4[(long)(m0 + m) * (K4D / 4) + k0 / 4 + kq];
        }
        #pragma unroll
        for (int i = 0; i < 4; ++i) {
            int kr = kr0 + i * 8;
            wv[i] = w4[(long)(k0 + kr) * (H1 / 4) + n0 / 4 + nq];
        }
        #pragma unroll
        for (int i = 0; i < 2; ++i) {
            int m = mrow + i * 16;
            *reinterpret_cast<float2*>(&fsh2[kq * 4 + 0][2 * m]) = make_float2(fv[i].x, fv[i].x);
            *reinterpret_cast<float2*>(&fsh2[kq * 4 + 1][2 * m]) = make_float2(fv[i].y, fv[i].y);
            *reinterpret_cast<float2*>(&fsh2[kq * 4 + 2][2 * m]) = make_float2(fv[i].z, fv[i].z);
            *reinterpret_cast<float2*>(&fsh2[kq * 4 + 3][2 * m]) = make_float2(fv[i].w, fv[i].w);
        }
        #pragma unroll
        for (int i = 0; i < 4; ++i) {
            int kr = kr0 + i * 8;
            *reinterpret_cast<float4*>(&wsh[kr][nq * 4]) = wv[i];
        }
        GRP_BAR();

        #pragma unroll
        for (int kt = 0; kt < NT; ++kt) {
            const int cur = kt & 1;
            const int nxt = cur ^ 1;

            if (kt + 1 < NT) {
                int kb = k0 + (kt + 1) * BK;
                #pragma unroll
                for (int i = 0; i < 2; ++i) {
                    int m = mrow + i * 16;
                    fv[i] = gf4[(long)(m0 + m) * (K4D / 4) + kb / 4 + kq];
                }
                #pragma unroll
                for (int i = 0; i < 4; ++i) {
                    int kr = kr0 + i * 8;
                    wv[i] = w4[(long)(kb + kr) * (H1 / 4) + n0 / 4 + nq];
                }
            }

            #pragma unroll
            for (int k = 0; k < BK; ++k) {
                const ulonglong2* fp =
                    reinterpret_cast<const ulonglong2*>(&fsh2[cur * BK + k][2 * (ty * 4)]);
                ulonglong2 fa = fp[0];
                ulonglong2 fb = fp[1];
                ulonglong2 wp = *reinterpret_cast<const ulonglong2*>(&wsh[cur * BK + k][tx * 4]);
                FFMA2(acc2[0][0], fa.x, wp.x);  FFMA2(acc2[0][1], fa.x, wp.y);
                FFMA2(acc2[1][0], fa.y, wp.x);  FFMA2(acc2[1][1], fa.y, wp.y);
                FFMA2(acc2[2][0], fb.x, wp.x);  FFMA2(acc2[2][1], fb.x, wp.y);
                FFMA2(acc2[3][0], fb.y, wp.x);  FFMA2(acc2[3][1], fb.y, wp.y);
            }

            if (kt + 1 < NT) {
                #pragma unroll
                for (int i = 0; i < 2; ++i) {
                    int m = mrow + i * 16;
                    *reinterpret_cast<float2*>(&fsh2[nxt * BK + kq * 4 + 0][2 * m]) = make_float2(fv[i].x, fv[i].x);
                    *reinterpret_cast<float2*>(&fsh2[nxt * BK + kq * 4 + 1][2 * m]) = make_float2(fv[i].y, fv[i].y);
                    *reinterpret_cast<float2*>(&fsh2[nxt * BK + kq * 4 + 2][2 * m]) = make_float2(fv[i].z, fv[i].z);
                    *reinterpret_cast<float2*>(&fsh2[nxt * BK + kq * 4 + 3][2 * m]) = make_float2(fv[i].w, fv[i].w);
                }
                #pragma unroll
                for (int i = 0; i < 4; ++i) {
                    int kr = kr0 + i * 8;
                    *reinterpret_cast<float4*>(&wsh[nxt * BK + kr][nq * 4]) = wv[i];
                }
                GRP_BAR();
            }
        }

        // epilogue: unpack, fold bias into split 0, store partials
        float* outp = g_h1p + (long)kz * (B * H1);
        #pragma unroll
        for (int r = 0; r < 4; ++r) {
            int m = m0 + ty * 4 + r;
            #pragma unroll
            for (int p = 0; p < 2; ++p) {
                int n = n0 + tx * 4 + p * 2;
                float lo = __uint_as_float((unsigned)(acc2[r][p] & 0xffffffffull));
                float hi = __uint_as_float((unsigned)(acc2[r][p] >> 32));
                if (kz == 0) { lo += b1[n]; hi += b1[n + 1]; }
                outp[(long)m * H1 + n]     = lo;
                outp[(long)m * H1 + n + 1] = hi;
            }
        }
    }

    grid_barrier();

    // =====================================================================
    // Phase 3: tail. Half-block per sample (2 samples/block).
    // Both halves run identical barrier sequences -> __syncthreads ok.
    // =====================================================================
    {
        const int samp = t >> 8;
        const int tt   = t & 255;
        const int b    = bx * 2 + samp;

        float* sbase = reinterpret_cast<float*>(dsm) + samp * 1024;
        float* hsh  = sbase;                  // 256
        float* p2sh = hsh + H1;               // [4][64]
        float* h2sh = p2sh + 4 * H2;          // 64
        float* lsh  = h2sh + H2;              // 4

        {
            float v = 0.f;
            #pragma unroll
            for (int p = 0; p < KS; ++p)
                v += g_h1p[(long)p * (B * H1) + (long)b * H1 + tt];
            hsh[tt] = fmaxf(v, 0.f);
        }
        __syncthreads();

        {
            const int j  = tt % H2;
            const int kg = tt / H2;
            float acc = 0.f;
            #pragma unroll 8
            for (int k = kg * 64; k < (kg + 1) * 64; ++k)
                acc = fmaf(hsh[k], W2[k * H2 + j], acc);
            p2sh[kg * H2 + j] = acc;
        }
        __syncthreads();

        if (tt < H2) {
            float acc = b2[tt] + p2sh[0 * H2 + tt] + p2sh[1 * H2 + tt]
                      + p2sh[2 * H2 + tt] + p2sh[3 * H2 + tt];
            h2sh[tt] = fmaxf(acc, 0.f);
        }
        __syncthreads();

        if (tt < L) {
            float acc = b3[tt];
            #pragma unroll
            for (int k = 0; k < H2; ++k)
                acc = fmaf(h2sh[k], W3[k * L + tt], acc);
            lsh[tt] = acc;
        }
        __syncthreads();

        if (tt < L) {
            float mx = lsh[0];
            #pragma unroll
            for (int l = 1; l < L; ++l) mx = fmaxf(mx, lsh[l]);
            float s = 0.f;
            #pragma unroll
            for (int l = 0; l < L; ++l) s += expf(lsh[l] - mx);
            out[b * L + tt] = expf(lsh[tt] - mx) / s;
        }
    }
}

// ---------------------------------------------------------------------------
extern "C" void kernel_launch(void* const* d_in, const int* in_sizes, int n_in,
                              void* d_out, int out_size)
{
    const float* x1 = (const float*)d_in[0];
    const float* x2 = (const float*)d_in[1];
    const int*   s1 = (const int*)d_in[2];
    const int*   e1 = (const int*)d_in[3];
    const int*   s2 = (const int*)d_in[4];
    const int*   e2 = (const int*)d_in[5];
    const float* W1 = (const float*)d_in[6];
    const float* b1 = (const float*)d_in[7];
    const float* W2 = (const float*)d_in[8];
    const float* b2 = (const float*)d_in[9];
    const float* W3 = (const float*)d_in[10];
    const float* b3 = (const float*)d_in[11];
    float* out = (float*)d_out;

    cudaFuncSetAttribute(fused_kernel,
                         cudaFuncAttributeMaxDynamicSharedMemorySize, DSM_BYTES);

    fused_kernel<<<GRID, 512, DSM_BYTES>>>(x1, x2, s1, e1, s2, e2,
                                           W1, b1, W2, b2, W3, b3, out);
}

// round 17
// speedup vs baseline: 1.6429x; 1.6429x over previous
#include <cuda_runtime.h>
#include <cuda_bf16.h>
#include <math.h>
#include <stdint.h>

// Problem constants
#define B   256
#define S   512
#define D   768
#define D4  192          // float4 per row
#define K4D 3072         // 4*D
#define H1  256
#define H2  64
#define L   4

// GEMM1 tiling: 128x64 tile, 8x8 micro-tile, split-K16
#define BM  128
#define BN  64
#define BK  16
#define KS  16
#define KC  (K4D/KS)     // 192 k per split
#define NT  (KC/BK)      // 12 k-tiles per job

// Scratch (device globals — no allocation allowed)
__device__ float g_f[B * K4D];            // features [256, 3072]
__device__ float g_h1p[KS * B * H1];      // GEMM1 partials [16, 256, 256]

__device__ __forceinline__ unsigned long long pack2(float x) {
    unsigned long long r;
    asm("mov.b64 %0, {%1, %1};" : "=l"(r) : "r"(__float_as_uint(x)));
    return r;
}
#define FFMA2(d, a, b) \
    asm("fma.rn.f32x2 %0, %1, %2, %0;" : "+l"(d) : "l"(a), "l"(b))

// ---------------------------------------------------------------------------
// K1: feature extraction (R9 version: 11.4us, 40 regs, 2 blocks/SM).
// grid (B, 2), 768 threads: col = t%192, rg = t/192 (4-way row split).
// ---------------------------------------------------------------------------
__global__ void __launch_bounds__(768) feat_kernel(
    const float* __restrict__ x1, const float* __restrict__ x2,
    const int* __restrict__ s1a, const int* __restrict__ e1a,
    const int* __restrict__ s2a, const int* __restrict__ e2a)
{
    __shared__ float4 part[4][D4];        // 12 KB

    const int b   = blockIdx.x;
    const int sel = blockIdx.y;
    const int t   = threadIdx.x;
    const int col = t % D4;
    const int rg  = t / D4;

    const float* x = sel ? x2 : x1;
    int s = sel ? s2a[b] : s1a[b];
    int e = sel ? e2a[b] : e1a[b];
    e = max(e, s + 1);
    int lo = max(s, 0), hi = min(e, S);
    int cnt = max(hi - lo, 1);
    float inv = 1.0f / (float)cnt;

    const float4* x4 = reinterpret_cast<const float4*>(x);
    float4* f4 = reinterpret_cast<float4*>(g_f);
    const long base = (long)b * S * D4;
    const long frow = (long)b * (K4D / 4) + sel * (2 * D4);

    if (rg == 0)
        f4[frow + col] = x4[base + col];

    float4 acc = make_float4(0.f, 0.f, 0.f, 0.f);
    const float4 zero = make_float4(0.f, 0.f, 0.f, 0.f);
    for (int r = lo + rg; r < hi; r += 16) {
        float4 v0, v1, v2, v3;
        v0 = x4[base + (long)r * D4 + col];
        v1 = (r + 4  < hi) ? x4[base + (long)(r + 4)  * D4 + col] : zero;
        v2 = (r + 8  < hi) ? x4[base + (long)(r + 8)  * D4 + col] : zero;
        v3 = (r + 12 < hi) ? x4[base + (long)(r + 12) * D4 + col] : zero;
        acc.x += (v0.x + v1.x) + (v2.x + v3.x);
        acc.y += (v0.y + v1.y) + (v2.y + v3.y);
        acc.z += (v0.z + v1.z) + (v2.z + v3.z);
        acc.w += (v0.w + v1.w) + (v2.w + v3.w);
    }
    part[rg][col] = acc;
    __syncthreads();

    if (t < D4) {
        float4 a0 = part[0][t], a1 = part[1][t], a2 = part[2][t], a3 = part[3][t];
        float4 o;
        o.x = (a0.x + a1.x + a2.x + a3.x) * inv;
        o.y = (a0.y + a1.y + a2.y + a3.y) * inv;
        o.z = (a0.z + a1.z + a2.z + a3.z) * inv;
        o.w = (a0.w + a1.w + a2.w + a3.w) * inv;
        f4[frow + D4 + t] = o;
    }
}

// ---------------------------------------------------------------------------
// K2: GEMM1 v2. 128x64 tile, 8x8 micro-tile per thread, FFMA2 with ALU-pipe
// packing (no duplicated smem). Per k per thread: 64B smem for 64 MACs.
// Double-buffered. grid (2, 4, KS=16) = 128 blocks, 128 threads.
// ---------------------------------------------------------------------------
__global__ void __launch_bounds__(128, 4) gemm1_kernel(
    const float* __restrict__ W1, const float* __restrict__ b1)
{
    __shared__ float fsh[2][BK][BM];      // 2 x 8 KB  (k-major, m contiguous)
    __shared__ float wsh[2][BK][BN];      // 2 x 4 KB

    const int m0 = blockIdx.x * BM;       // 0 or 128
    const int n0 = blockIdx.y * BN;       // 0..192
    const int kz = blockIdx.z;            // 0..15
    const int k0 = kz * KC;

    const int tid = threadIdx.x;
    const int tx = tid & 7;               // n group: 8 cols each
    const int ty = tid >> 3;              // m group: 8 rows each (0..15)

    const float4* gf4 = reinterpret_cast<const float4*>(g_f);
    const float4* w4  = reinterpret_cast<const float4*>(W1);

    // loader indices
    // f: thread loads row (m0 + tid), 4 float4 along k (16 k-values)
    // w: row kr = ty (0..15), float4 cols nq=tx and tx+8
    unsigned long long acc[8][4];
    #pragma unroll
    for (int r = 0; r < 8; ++r)
        #pragma unroll
        for (int p = 0; p < 4; ++p) acc[r][p] = 0ull;

    float4 fv[4];
    float4 wv[2];

    // ---- prologue: load + stage k-tile 0 ----
    #pragma unroll
    for (int q = 0; q < 4; ++q)
        fv[q] = gf4[(long)(m0 + tid) * (K4D / 4) + (k0 >> 2) + q];
    #pragma unroll
    for (int i = 0; i < 2; ++i)
        wv[i] = w4[(long)(k0 + ty) * (H1 / 4) + (n0 >> 2) + tx + i * 8];

    #pragma unroll
    for (int q = 0; q < 4; ++q) {
        fsh[0][q * 4 + 0][tid] = fv[q].x;
        fsh[0][q * 4 + 1][tid] = fv[q].y;
        fsh[0][q * 4 + 2][tid] = fv[q].z;
        fsh[0][q * 4 + 3][tid] = fv[q].w;
    }
    #pragma unroll
    for (int i = 0; i < 2; ++i)
        *reinterpret_cast<float4*>(&wsh[0][ty][(tx + i * 8) * 4]) = wv[i];
    __syncthreads();

    // ---- main loop ----
    #pragma unroll
    for (int kt = 0; kt < NT; ++kt) {
        const int cur = kt & 1;
        const int nxt = cur ^ 1;

        if (kt + 1 < NT) {
            int kb = k0 + (kt + 1) * BK;
            #pragma unroll
            for (int q = 0; q < 4; ++q)
                fv[q] = gf4[(long)(m0 + tid) * (K4D / 4) + (kb >> 2) + q];
            #pragma unroll
            for (int i = 0; i < 2; ++i)
                wv[i] = w4[(long)(kb + ty) * (H1 / 4) + (n0 >> 2) + tx + i * 8];
        }

        #pragma unroll
        for (int k = 0; k < BK; ++k) {
            float4 ra = *reinterpret_cast<const float4*>(&fsh[cur][k][ty * 8]);
            float4 rb = *reinterpret_cast<const float4*>(&fsh[cur][k][ty * 8 + 4]);
            ulonglong2 wp0 = *reinterpret_cast<const ulonglong2*>(&wsh[cur][k][tx * 8]);
            ulonglong2 wp1 = *reinterpret_cast<const ulonglong2*>(&wsh[cur][k][tx * 8 + 4]);

            unsigned long long f0 = pack2(ra.x), f1 = pack2(ra.y);
            unsigned long long f2 = pack2(ra.z), f3 = pack2(ra.w);
            unsigned long long f4_ = pack2(rb.x), f5 = pack2(rb.y);
            unsigned long long f6 = pack2(rb.z), f7 = pack2(rb.w);

            FFMA2(acc[0][0], f0, wp0.x); FFMA2(acc[0][1], f0, wp0.y);
            FFMA2(acc[0][2], f0, wp1.x); FFMA2(acc[0][3], f0, wp1.y);
            FFMA2(acc[1][0], f1, wp0.x); FFMA2(acc[1][1], f1, wp0.y);
            FFMA2(acc[1][2], f1, wp1.x); FFMA2(acc[1][3], f1, wp1.y);
            FFMA2(acc[2][0], f2, wp0.x); FFMA2(acc[2][1], f2, wp0.y);
            FFMA2(acc[2][2], f2, wp1.x); FFMA2(acc[2][3], f2, wp1.y);
            FFMA2(acc[3][0], f3, wp0.x); FFMA2(acc[3][1], f3, wp0.y);
            FFMA2(acc[3][2], f3, wp1.x); FFMA2(acc[3][3], f3, wp1.y);
            FFMA2(acc[4][0], f4_, wp0.x); FFMA2(acc[4][1], f4_, wp0.y);
            FFMA2(acc[4][2], f4_, wp1.x); FFMA2(acc[4][3], f4_, wp1.y);
            FFMA2(acc[5][0], f5, wp0.x); FFMA2(acc[5][1], f5, wp0.y);
            FFMA2(acc[5][2], f5, wp1.x); FFMA2(acc[5][3], f5, wp1.y);
            FFMA2(acc[6][0], f6, wp0.x); FFMA2(acc[6][1], f6, wp0.y);
            FFMA2(acc[6][2], f6, wp1.x); FFMA2(acc[6][3], f6, wp1.y);
            FFMA2(acc[7][0], f7, wp0.x); FFMA2(acc[7][1], f7, wp0.y);
            FFMA2(acc[7][2], f7, wp1.x); FFMA2(acc[7][3], f7, wp1.y);
        }

        if (kt + 1 < NT) {
            #pragma unroll
            for (int q = 0; q < 4; ++q) {
                fsh[nxt][q * 4 + 0][tid] = fv[q].x;
                fsh[nxt][q * 4 + 1][tid] = fv[q].y;
                fsh[nxt][q * 4 + 2][tid] = fv[q].z;
                fsh[nxt][q * 4 + 3][tid] = fv[q].w;
            }
            #pragma unroll
            for (int i = 0; i < 2; ++i)
                *reinterpret_cast<float4*>(&wsh[nxt][ty][(tx + i * 8) * 4]) = wv[i];
            __syncthreads();
        }
    }

    // ---- epilogue: unpack, fold bias into split 0, store partials ----
    float* outp = g_h1p + (long)kz * (B * H1);
    const int nb = n0 + tx * 8;
    float bias[8];
    if (kz == 0) {
        #pragma unroll
        for (int j = 0; j < 8; ++j) bias[j] = b1[nb + j];
    } else {
        #pragma unroll
        for (int j = 0; j < 8; ++j) bias[j] = 0.f;
    }
    #pragma unroll
    for (int r = 0; r < 8; ++r) {
        const int m = m0 + ty * 8 + r;
        float4 o0, o1;
        o0.x = __uint_as_float((unsigned)(acc[r][0] & 0xffffffffull)) + bias[0];
        o0.y = __uint_as_float((unsigned)(acc[r][0] >> 32))           + bias[1];
        o0.z = __uint_as_float((unsigned)(acc[r][1] & 0xffffffffull)) + bias[2];
        o0.w = __uint_as_float((unsigned)(acc[r][1] >> 32))           + bias[3];
        o1.x = __uint_as_float((unsigned)(acc[r][2] & 0xffffffffull)) + bias[4];
        o1.y = __uint_as_float((unsigned)(acc[r][2] >> 32))           + bias[5];
        o1.z = __uint_as_float((unsigned)(acc[r][3] & 0xffffffffull)) + bias[6];
        o1.w = __uint_as_float((unsigned)(acc[r][3] >> 32))           + bias[7];
        *reinterpret_cast<float4*>(&outp[(long)m * H1 + nb])     = o0;
        *reinterpret_cast<float4*>(&outp[(long)m * H1 + nb + 4]) = o1;
    }
}

// ---------------------------------------------------------------------------
// K3: per-batch fused tail: reduce split-K partials + ReLU -> GEMM2 + ReLU ->
// GEMM3 -> softmax. One block per batch sample, 256 threads.
// ---------------------------------------------------------------------------
__global__ void __launch_bounds__(H1) tail_kernel(
    const float* __restrict__ W2, const float* __restrict__ b2,
    const float* __restrict__ W3, const float* __restrict__ b3,
    float* __restrict__ out)
{
    __shared__ float hsh[H1];
    __shared__ float p2sh[4][H2];
    __shared__ float h2sh[H2];
    __shared__ float lsh[L];

    const int b = blockIdx.x;
    const int t = threadIdx.x;

    {
        float v = 0.f;
        #pragma unroll
        for (int p = 0; p < KS; ++p)
            v += g_h1p[(long)p * (B * H1) + (long)b * H1 + t];
        hsh[t] = fmaxf(v, 0.f);
    }
    __syncthreads();

    {
        const int j  = t % H2;
        const int kg = t / H2;
        float acc = 0.f;
        #pragma unroll 8
        for (int k = kg * 64; k < (kg + 1) * 64; ++k)
            acc = fmaf(hsh[k], W2[k * H2 + j], acc);
        p2sh[kg][j] = acc;
    }
    __syncthreads();

    if (t < H2) {
        float acc = b2[t] + p2sh[0][t] + p2sh[1][t] + p2sh[2][t] + p2sh[3][t];
        h2sh[t] = fmaxf(acc, 0.f);
    }
    __syncthreads();

    if (t < L) {
        float acc = b3[t];
        #pragma unroll
        for (int k = 0; k < H2; ++k)
            acc = fmaf(h2sh[k], W3[k * L + t], acc);
        lsh[t] = acc;
    }
    __syncthreads();

    if (t < L) {
        float mx = lsh[0];
        #pragma unroll
        for (int l = 1; l < L; ++l) mx = fmaxf(mx, lsh[l]);
        float s = 0.f;
        #pragma unroll
        for (int l = 0; l < L; ++l) s += expf(lsh[l] - mx);
        out[b * L + t] = expf(lsh[t] - mx) / s;
    }
}

// ---------------------------------------------------------------------------
extern "C" void kernel_launch(void* const* d_in, const int* in_sizes, int n_in,
                              void* d_out, int out_size)
{
    const float* x1 = (const float*)d_in[0];
    const float* x2 = (const float*)d_in[1];
    const int*   s1 = (const int*)d_in[2];
    const int*   e1 = (const int*)d_in[3];
    const int*   s2 = (const int*)d_in[4];
    const int*   e2 = (const int*)d_in[5];
    const float* W1 = (const float*)d_in[6];
    const float* b1 = (const float*)d_in[7];
    const float* W2 = (const float*)d_in[8];
    const float* b2 = (const float*)d_in[9];
    const float* W3 = (const float*)d_in[10];
    const float* b3 = (const float*)d_in[11];
    float* out = (float*)d_out;

    feat_kernel<<<dim3(B, 2), 768>>>(x1, x2, s1, e1, s2, e2);
    gemm1_kernel<<<dim3(B / BM, H1 / BN, KS), 128>>>(W1, b1);
    tail_kernel<<<B, H1>>>(W2, b2, W3, b3, out);
}